// round 3
// baseline (speedup 1.0000x reference)
#include <cuda_runtime.h>

#define NSAMPLE 32
#define RADIUS2 1.0f
#define MAXN    8192

__device__ int g_ball_idx[MAXN * NSAMPLE];
__device__ int g_count[MAXN];
__device__ int g_offset[MAXN];
__device__ int g_total;
__device__ int g_done;   // zero-initialized; self-resets each run

// ---------------------------------------------------------------------------
// Kernel 1: phase-1 ball query (warp per point); last block scans counts.
// ---------------------------------------------------------------------------
__global__ void query_kernel(const float* __restrict__ xyz,
                             const float* __restrict__ new_xyz,
                             const float* __restrict__ rois,
                             int PB, int Nb, int M, int K, int N) {
    int lane = threadIdx.x & 31;
    int wid  = threadIdx.x >> 5;
    int p    = blockIdx.x * (blockDim.x >> 5) + wid;

    if (p < N) {
        const int b = p / Nb;
        const float px = xyz[3 * p + 0];
        const float py = xyz[3 * p + 1];
        const float pz = xyz[3 * p + 2];
        int count = 0;
        const int base_flat = b * M * K;

        for (int mr = 0; mr < M && count < NSAMPLE; mr += 32) {
            int m_l = mr + lane;
            bool inb = false;
            if (m_l < M) {
                const float* ro = rois + (size_t)(b * M + m_l) * 7;
                float dx = px - ro[0], dy = py - ro[1], dz = pz - ro[2];
                float da = ro[3], db = ro[4], dc = ro[5];
                inb = (dx * dx + dy * dy + dz * dz) <= (da * da + db * db + dc * dc);
            }
            unsigned bm = __ballot_sync(0xffffffffu, inb);
            while (bm && count < NSAMPLE) {
                int m = mr + __ffs(bm) - 1;
                bm &= bm - 1;
                const float* gp = new_xyz + (size_t)(base_flat + m * K) * 3;
                for (int kb = 0; kb < K && count < NSAMPLE; kb += 32) {
                    int k = kb + lane;
                    bool hit = false;
                    if (k < K) {
                        float dx = px - gp[3 * k + 0];
                        float dy = py - gp[3 * k + 1];
                        float dz = pz - gp[3 * k + 2];
                        hit = (dx * dx + dy * dy + dz * dz) <= RADIUS2;
                    }
                    unsigned hm = __ballot_sync(0xffffffffu, hit);
                    if (hit) {
                        int rank = count + __popc(hm & ((1u << lane) - 1u));
                        if (rank < NSAMPLE)
                            g_ball_idx[p * NSAMPLE + rank] = base_flat + m * K + k;
                    }
                    count += __popc(hm);
                }
            }
        }
        if (lane == 0) g_count[p] = count < NSAMPLE ? count : NSAMPLE;
    }

    // ---- last block performs the exclusive scan ----
    __shared__ int s_last;
    __shared__ int s_wsum[8];
    __syncthreads();
    if (threadIdx.x == 0) {
        __threadfence();
        s_last = (atomicAdd(&g_done, 1) == PB - 1) ? 1 : 0;
    }
    __syncthreads();
    if (!s_last) return;

    {
        const int T = blockDim.x;            // 256
        int tid  = threadIdx.x;
        int per  = (N + T - 1) / T;          // <= 32
        int base = tid * per;
        int loc[32];
        int sum = 0;
        for (int i = 0; i < per; i++) {
            int idx = base + i;
            int v = (idx < N) ? g_count[idx] : 0;
            loc[i] = sum;
            sum += v;
        }
        int l2 = tid & 31, w = tid >> 5;
        int x = sum;
        #pragma unroll
        for (int off = 1; off < 32; off <<= 1) {
            int y = __shfl_up_sync(0xffffffffu, x, off);
            if (l2 >= off) x += y;
        }
        if (l2 == 31) s_wsum[w] = x;
        __syncthreads();
        if (w == 0 && l2 < 8) {
            int v = s_wsum[l2];
            #pragma unroll
            for (int off = 1; off < 8; off <<= 1) {
                int y = __shfl_up_sync(0xffu, v, off);
                if (l2 >= off) v += y;
            }
            s_wsum[l2] = v;
        }
        __syncthreads();
        int excl = x - sum + (w > 0 ? s_wsum[w - 1] : 0);
        for (int i = 0; i < per; i++) {
            int idx = base + i;
            if (idx < N) g_offset[idx] = excl + loc[i];
        }
        __syncthreads();
        if (threadIdx.x == 0) {
            g_total = g_offset[N - 1] + g_count[N - 1];
            g_done  = 0;   // reset for next graph replay
        }
    }
}

// ---------------------------------------------------------------------------
// Kernel 2: blocks [0,N): block-per-point gather + row writes (4 warps share
// the <=32 rows). Blocks [N, N+ZB): grid-stride zero of the invalid tail
// (rows >= nind and index tail), using g_total from kernel 1.
// ---------------------------------------------------------------------------
__device__ __forceinline__ void zero_range(float* __restrict__ out,
                                           long start, long end,
                                           int bid, int nblk) {
    if (end <= start) return;
    long s4 = (start + 3) & ~3L;
    if (s4 > end) s4 = end;
    long e4 = s4 + (((end - s4) >> 2) << 2);
    if (bid == 0) {
        int head = (int)(s4 - start);
        if ((int)threadIdx.x < head) out[start + threadIdx.x] = 0.f;
        int tail = (int)(end - e4);
        if (threadIdx.x >= 4 && (int)threadIdx.x < 4 + tail)
            out[e4 + threadIdx.x - 4] = 0.f;
    }
    long n4 = (e4 - s4) >> 2;
    long stride = (long)nblk * blockDim.x;
    float4 z = make_float4(0.f, 0.f, 0.f, 0.f);
    for (long i = (long)bid * blockDim.x + threadIdx.x; i < n4; i += stride)
        reinterpret_cast<float4*>(out + s4)[i] = z;
}

__global__ void write_kernel(const float* __restrict__ xyz,
                             const float* __restrict__ new_xyz,
                             const float* __restrict__ features,
                             float* __restrict__ out,
                             int N, int C, int ZB, int write_idx,
                             long idx_base, long L, long out_sz) {
    const int CC = 3 + C;   // 35

    if ((int)blockIdx.x >= N) {
        // ---- zero tail blocks ----
        int zb = blockIdx.x - N;
        long total = (long)g_total;
        long gf_end = idx_base < out_sz ? idx_base : out_sz;   // L*CC (cap)
        zero_range(out, total * CC, gf_end, zb, ZB);
        if (out_sz > idx_base)
            zero_range(out, idx_base + total, out_sz, zb, ZB);
        return;
    }

    const int p = blockIdx.x;
    __shared__ int   s_count, s_off;
    __shared__ float s_row[40];      // row template: [0..2] unused, [3..34]=feat
    __shared__ float s_gx[NSAMPLE], s_gy[NSAMPLE], s_gz[NSAMPLE];
    __shared__ int   s_gs[NSAMPLE];
    __shared__ float s_p[3];

    int t = threadIdx.x;
    if (t == 0) { s_count = g_count[p]; s_off = g_offset[p]; }
    __syncthreads();
    const int count = s_count;
    if (count == 0) return;

    if (t < C) s_row[3 + t] = features[(size_t)p * C + t];
    if (t < 3) s_p[t] = xyz[3 * p + t];
    if (t < count) {
        int g = g_ball_idx[p * NSAMPLE + t];
        s_gs[t] = g;
        const float* np_ = new_xyz + 3 * (size_t)g;
        s_gx[t] = np_[0]; s_gy[t] = np_[1]; s_gz[t] = np_[2];
    }
    __syncthreads();

    const int off  = s_off;
    const int lane = t & 31;
    const int w    = t >> 5;
    const int nw   = blockDim.x >> 5;

    for (int r = w; r < count; r += nw) {
        float* o = out + (size_t)(off + r) * CC;
        float v;
        if (lane == 0)      v = s_p[0] - s_gx[r];
        else if (lane == 1) v = s_p[1] - s_gy[r];
        else if (lane == 2) v = s_p[2] - s_gz[r];
        else                v = s_row[lane];
        o[lane] = v;
        if (lane < CC - 32) o[32 + lane] = s_row[32 + lane];
    }

    if (write_idx && t < count)
        out[idx_base + off + t] = (float)s_gs[t];
}

// ---------------------------------------------------------------------------
extern "C" void kernel_launch(void* const* d_in, const int* in_sizes, int n_in,
                              void* d_out, int out_size) {
    const float* xyz      = (const float*)d_in[0];
    const float* new_xyz  = (const float*)d_in[2];
    const float* rois     = (const float*)d_in[3];
    const float* features = (const float*)d_in[4];

    const int B  = in_sizes[1];
    const int N  = in_sizes[0] / 3;
    const int Nb = N / B;
    const int M  = in_sizes[3] / (B * 7);
    const int K  = in_sizes[2] / (B * M * 3);
    const int C  = in_sizes[4] / N;
    const long L = (long)N * NSAMPLE;
    const int CC = 3 + C;

    float* out = (float*)d_out;

    const int TPB1 = 256;
    const int PB   = (N + (TPB1 >> 5) - 1) / (TPB1 >> 5);
    query_kernel<<<PB, TPB1>>>(xyz, new_xyz, rois, PB, Nb, M, K, N);

    const int TPB2 = 128;
    const int ZB   = 256;
    int write_idx  = ((long)out_size >= L * CC + L) ? 1 : 0;
    write_kernel<<<N + ZB, TPB2>>>(xyz, new_xyz, features, out,
                                   N, C, ZB, write_idx,
                                   L * (long)CC, L, (long)out_size);
}

// round 4
// speedup vs baseline: 1.3138x; 1.3138x over previous
#include <cuda_runtime.h>

#define NSAMPLE 32
#define RADIUS2 1.0f
#define MAXN    8192
#define MAXCH   7      // max prefetched 32-wide chunks per roi (K<=224)

__device__ int g_ball_idx[MAXN * NSAMPLE];
__device__ int g_count[MAXN];
__device__ int g_offset[MAXN];
__device__ int g_total;
__device__ int g_done;   // zero-initialized; self-resets each run

// ---------------------------------------------------------------------------
// Kernel 1: ball query, warp per point. Coarse roi test from smem; fine test
// prefetches a full roi's grid points (MLP up to 21) before any ballot.
// Last block performs the exclusive scan of counts.
// ---------------------------------------------------------------------------
__global__ void query_kernel(const float* __restrict__ xyz,
                             const float* __restrict__ new_xyz,
                             const float* __restrict__ rois,
                             int PB, int Nb, int M, int K, int N, int BM) {
    __shared__ float4 s_roi[256];     // (cx,cy,cz,r2) per roi, BM <= 256

    int tid  = threadIdx.x;
    if (tid < BM) {
        const float* ro = rois + (size_t)tid * 7;
        float da = ro[3], db = ro[4], dc = ro[5];
        s_roi[tid] = make_float4(ro[0], ro[1], ro[2],
                                 da * da + db * db + dc * dc);
    }
    __syncthreads();

    int lane = tid & 31;
    int wid  = tid >> 5;
    int p    = blockIdx.x * (blockDim.x >> 5) + wid;

    if (p < N) {
        const int b = p / Nb;
        const float px = __ldg(&xyz[3 * p + 0]);
        const float py = __ldg(&xyz[3 * p + 1]);
        const float pz = __ldg(&xyz[3 * p + 2]);
        int count = 0;
        const int base_flat = b * M * K;
        const int nch = (K + 31) >> 5;

        for (int mr = 0; mr < M && count < NSAMPLE; mr += 32) {
            int m_l = mr + lane;
            bool inb = false;
            if (m_l < M) {
                float4 rc = s_roi[b * M + m_l];
                float dx = px - rc.x, dy = py - rc.y, dz = pz - rc.z;
                inb = (dx * dx + dy * dy + dz * dz) <= rc.w;
            }
            unsigned bm = __ballot_sync(0xffffffffu, inb);
            while (bm) {
                int m = mr + __ffs(bm) - 1;
                bm &= bm - 1;
                const float* gp = new_xyz + (size_t)(base_flat + m * K) * 3;

                for (int c0 = 0; c0 < nch; c0 += MAXCH) {
                    int nc = nch - c0; if (nc > MAXCH) nc = MAXCH;
                    float ax[MAXCH], ay[MAXCH], az[MAXCH];
                    // prefetch: all loads issued before first ballot
                    #pragma unroll
                    for (int c = 0; c < MAXCH; c++) {
                        if (c < nc) {
                            int k = (c0 + c) * 32 + lane;
                            if (k < K) {
                                ax[c] = __ldg(&gp[3 * k + 0]);
                                ay[c] = __ldg(&gp[3 * k + 1]);
                                az[c] = __ldg(&gp[3 * k + 2]);
                            } else {
                                ax[c] = 1e30f; ay[c] = 1e30f; az[c] = 1e30f;
                            }
                        }
                    }
                    #pragma unroll
                    for (int c = 0; c < MAXCH; c++) {
                        if (c < nc) {
                            int k = (c0 + c) * 32 + lane;
                            float dx = px - ax[c];
                            float dy = py - ay[c];
                            float dz = pz - az[c];
                            bool hit = (dx * dx + dy * dy + dz * dz) <= RADIUS2;
                            unsigned hm = __ballot_sync(0xffffffffu, hit);
                            if (hit) {
                                int rank = count + __popc(hm & ((1u << lane) - 1u));
                                if (rank < NSAMPLE)
                                    g_ball_idx[p * NSAMPLE + rank] =
                                        base_flat + m * K + k;
                            }
                            count += __popc(hm);
                        }
                    }
                }
                if (count >= NSAMPLE) break;
            }
        }
        if (lane == 0) g_count[p] = count < NSAMPLE ? count : NSAMPLE;
    }

    // ---- last block performs the exclusive scan ----
    __shared__ int s_last;
    __shared__ int s_wsum[8];
    __syncthreads();
    if (threadIdx.x == 0) {
        __threadfence();
        s_last = (atomicAdd(&g_done, 1) == PB - 1) ? 1 : 0;
    }
    __syncthreads();
    if (!s_last) return;

    {
        const int T = blockDim.x;            // 256
        int t    = threadIdx.x;
        int per  = (N + T - 1) / T;          // <= 32
        int base = t * per;
        int loc[32];
        int sum = 0;
        for (int i = 0; i < per; i++) {
            int idx = base + i;
            int v = (idx < N) ? g_count[idx] : 0;
            loc[i] = sum;
            sum += v;
        }
        int l2 = t & 31, w = t >> 5;
        int x = sum;
        #pragma unroll
        for (int off = 1; off < 32; off <<= 1) {
            int y = __shfl_up_sync(0xffffffffu, x, off);
            if (l2 >= off) x += y;
        }
        if (l2 == 31) s_wsum[w] = x;
        __syncthreads();
        if (w == 0 && l2 < 8) {
            int v = s_wsum[l2];
            #pragma unroll
            for (int off = 1; off < 8; off <<= 1) {
                int y = __shfl_up_sync(0xffu, v, off);
                if (l2 >= off) v += y;
            }
            s_wsum[l2] = v;
        }
        __syncthreads();
        int excl = x - sum + (w > 0 ? s_wsum[w - 1] : 0);
        for (int i = 0; i < per; i++) {
            int idx = base + i;
            if (idx < N) g_offset[idx] = excl + loc[i];
        }
        __syncthreads();
        if (threadIdx.x == 0) {
            g_total = g_offset[N - 1] + g_count[N - 1];
            g_done  = 0;   // reset for next graph replay
        }
    }
}

// ---------------------------------------------------------------------------
// Kernel 2: blocks [0,WB): 2 warps per point, each handles alternating rows.
// Blocks [WB, WB+ZB): grid-stride zero of the invalid tail using g_total.
// ---------------------------------------------------------------------------
__device__ __forceinline__ void zero_range(float* __restrict__ out,
                                           long start, long end,
                                           int bid, int nblk) {
    if (end <= start) return;
    long s4 = (start + 3) & ~3L;
    if (s4 > end) s4 = end;
    long e4 = s4 + (((end - s4) >> 2) << 2);
    if (bid == 0) {
        int head = (int)(s4 - start);
        if ((int)threadIdx.x < head) out[start + threadIdx.x] = 0.f;
        int tail = (int)(end - e4);
        if (threadIdx.x >= 4 && (int)threadIdx.x < 4 + tail)
            out[e4 + threadIdx.x - 4] = 0.f;
    }
    long n4 = (e4 - s4) >> 2;
    long stride = (long)nblk * blockDim.x;
    float4 z = make_float4(0.f, 0.f, 0.f, 0.f);
    for (long i = (long)bid * blockDim.x + threadIdx.x; i < n4; i += stride)
        reinterpret_cast<float4*>(out + s4)[i] = z;
}

__global__ void write_kernel(const float* __restrict__ xyz,
                             const float* __restrict__ new_xyz,
                             const float* __restrict__ features,
                             float* __restrict__ out,
                             int N, int C, int WB, int ZB, int write_idx,
                             long idx_base, long out_sz) {
    const int CC = 3 + C;   // 35

    if ((int)blockIdx.x >= WB) {
        int zb = blockIdx.x - WB;
        long total = (long)g_total;
        long gf_end = idx_base < out_sz ? idx_base : out_sz;
        zero_range(out, total * CC, gf_end, zb, ZB);
        if (out_sz > idx_base)
            zero_range(out, idx_base + total, out_sz, zb, ZB);
        return;
    }

    int tid  = threadIdx.x;
    int lane = tid & 31;
    int gw   = blockIdx.x * (blockDim.x >> 5) + (tid >> 5);
    int p    = gw >> 1;            // point
    int h    = gw & 1;             // half: rows h, h+2, ...
    if (p >= N) return;

    int count = g_count[p];
    if (count == 0) return;
    int off = g_offset[p];

    float f = __ldg(&features[(size_t)p * C + lane]);

    int   gs = 0;
    float nx = 0.f, ny = 0.f, nz = 0.f;
    if (lane < count) {
        gs = g_ball_idx[p * NSAMPLE + lane];
        const float* np_ = new_xyz + 3 * (size_t)gs;
        nx = __ldg(&np_[0]); ny = __ldg(&np_[1]); nz = __ldg(&np_[2]);
    }

    float px = __ldg(&xyz[3 * p + 0]);
    float py = __ldg(&xyz[3 * p + 1]);
    float pz = __ldg(&xyz[3 * p + 2]);

    float fshift = __shfl_sync(0xffffffffu, f, (lane - 3) & 31);
    float ftail  = __shfl_sync(0xffffffffu, f, (29 + lane) & 31);

    for (int r = h; r < count; r += 2) {
        float sx = __shfl_sync(0xffffffffu, nx, r);
        float sy = __shfl_sync(0xffffffffu, ny, r);
        float sz = __shfl_sync(0xffffffffu, nz, r);
        float v;
        if (lane == 0)      v = px - sx;
        else if (lane == 1) v = py - sy;
        else if (lane == 2) v = pz - sz;
        else                v = fshift;
        float* o = out + (size_t)(off + r) * CC;
        o[lane] = v;
        if (lane < 3) o[32 + lane] = ftail;
    }

    if (write_idx && h == 0 && lane < count)
        out[idx_base + off + lane] = (float)gs;
}

// ---------------------------------------------------------------------------
extern "C" void kernel_launch(void* const* d_in, const int* in_sizes, int n_in,
                              void* d_out, int out_size) {
    const float* xyz      = (const float*)d_in[0];
    const float* new_xyz  = (const float*)d_in[2];
    const float* rois     = (const float*)d_in[3];
    const float* features = (const float*)d_in[4];

    const int B  = in_sizes[1];
    const int N  = in_sizes[0] / 3;
    const int Nb = N / B;
    const int M  = in_sizes[3] / (B * 7);
    const int K  = in_sizes[2] / (B * M * 3);
    const int C  = in_sizes[4] / N;
    const long L = (long)N * NSAMPLE;
    const int CC = 3 + C;
    const int BM = B * M;

    float* out = (float*)d_out;

    const int TPB = 256;
    const int PB  = (N + (TPB >> 5) - 1) / (TPB >> 5);     // warp per point
    query_kernel<<<PB, TPB>>>(xyz, new_xyz, rois, PB, Nb, M, K, N, BM);

    const int WPB = TPB >> 5;                               // 8 warps/block
    const int WB  = (2 * N + WPB - 1) / WPB;                // 2 warps per point
    const int ZB  = 256;
    int write_idx = ((long)out_size >= L * CC + L) ? 1 : 0;
    write_kernel<<<WB + ZB, TPB>>>(xyz, new_xyz, features, out,
                                   N, C, WB, ZB, write_idx,
                                   L * (long)CC, (long)out_size);
}

// round 5
// speedup vs baseline: 1.4325x; 1.0904x over previous
#include <cuda_runtime.h>

#define NSAMPLE 32
#define RADIUS2 1.0f
#define MAXN    8192
#define NCH     7       // 32-wide chunks per roi pass (covers K<=224 per pass)

__device__ float4 g_ball[MAXN * NSAMPLE];   // (dx,dy,dz, idx-as-float)
__device__ int    g_count[MAXN];
__device__ int    g_offc[MAXN];             // (offset<<6) | count
__device__ int    g_total;
__device__ int    g_done;                   // zero-init; self-resets each run

// ---------------------------------------------------------------------------
// Kernel 1: ball query, warp per point. Coarse test = 2 ballots over smem
// rois -> 64-bit mask; fine test prefetches up to TWO rois' grid points
// (42x3 loads) before any ballot. Hits store (dx,dy,dz,g) directly.
// Last block performs the exclusive scan of counts.
// ---------------------------------------------------------------------------
__global__ void query_kernel(const float* __restrict__ xyz,
                             const float* __restrict__ new_xyz,
                             const float* __restrict__ rois,
                             int PB, int Nb, int M, int K, int N, int BM) {
    __shared__ float4 s_roi[256];     // (cx,cy,cz,r2), BM <= 256

    int tid = threadIdx.x;
    if (tid < BM) {
        const float* ro = rois + (size_t)tid * 7;
        float da = ro[3], db = ro[4], dc = ro[5];
        s_roi[tid] = make_float4(ro[0], ro[1], ro[2],
                                 da * da + db * db + dc * dc);
    }
    __syncthreads();

    int lane = tid & 31;
    int wid  = tid >> 5;
    int p    = blockIdx.x * (blockDim.x >> 5) + wid;

    if (p < N) {
        const int b = p / Nb;
        const float px = __ldg(&xyz[3 * p + 0]);
        const float py = __ldg(&xyz[3 * p + 1]);
        const float pz = __ldg(&xyz[3 * p + 2]);
        int count = 0;
        const int base_flat = b * M * K;

        for (int mg = 0; mg < M && count < NSAMPLE; mg += 64) {
            // ---- coarse: 64 rois via two ballots (smem, no mem latency) ----
            bool c0 = false, c1 = false;
            int m0 = mg + lane, m1 = mg + 32 + lane;
            if (m0 < M) {
                float4 rc = s_roi[b * M + m0];
                float dx = px - rc.x, dy = py - rc.y, dz = pz - rc.z;
                c0 = (dx * dx + dy * dy + dz * dz) <= rc.w;
            }
            if (m1 < M) {
                float4 rc = s_roi[b * M + m1];
                float dx = px - rc.x, dy = py - rc.y, dz = pz - rc.z;
                c1 = (dx * dx + dy * dy + dz * dz) <= rc.w;
            }
            unsigned long long mask =
                ((unsigned long long)__ballot_sync(0xffffffffu, c1) << 32) |
                (unsigned long long)__ballot_sync(0xffffffffu, c0);

            while (mask && count < NSAMPLE) {
                int mA = __ffsll(mask) - 1; mask &= mask - 1;
                int mB = -1;
                if (mask) { mB = __ffsll(mask) - 1; mask &= mask - 1; }
                const int gmA = mg + mA;
                const int gmB = (mB >= 0) ? (mg + mB) : 0;

                for (int k0 = 0; k0 < K; k0 += NCH * 32) {
                    // ---- prefetch roi A (and B) before any ballot ----
                    const float* gpA = new_xyz + (size_t)(base_flat + gmA * K) * 3;
                    const float* gpB = new_xyz + (size_t)(base_flat + gmB * K) * 3;
                    float axA[NCH], ayA[NCH], azA[NCH];
                    float axB[NCH], ayB[NCH], azB[NCH];
                    #pragma unroll
                    for (int c = 0; c < NCH; c++) {
                        int k = k0 + c * 32 + lane;
                        bool v = k < K;
                        axA[c] = v ? __ldg(&gpA[3 * k + 0]) : 1e30f;
                        ayA[c] = v ? __ldg(&gpA[3 * k + 1]) : 1e30f;
                        azA[c] = v ? __ldg(&gpA[3 * k + 2]) : 1e30f;
                    }
                    if (mB >= 0) {
                        #pragma unroll
                        for (int c = 0; c < NCH; c++) {
                            int k = k0 + c * 32 + lane;
                            bool v = k < K;
                            axB[c] = v ? __ldg(&gpB[3 * k + 0]) : 1e30f;
                            ayB[c] = v ? __ldg(&gpB[3 * k + 1]) : 1e30f;
                            azB[c] = v ? __ldg(&gpB[3 * k + 2]) : 1e30f;
                        }
                    }
                    // ---- process A ----
                    #pragma unroll
                    for (int c = 0; c < NCH; c++) {
                        int k = k0 + c * 32 + lane;
                        float dx = px - axA[c];
                        float dy = py - ayA[c];
                        float dz = pz - azA[c];
                        bool hit = (dx * dx + dy * dy + dz * dz) <= RADIUS2;
                        unsigned hm = __ballot_sync(0xffffffffu, hit);
                        if (hit) {
                            int rank = count + __popc(hm & ((1u << lane) - 1u));
                            if (rank < NSAMPLE)
                                g_ball[p * NSAMPLE + rank] =
                                    make_float4(dx, dy, dz,
                                                (float)(base_flat + gmA * K + k));
                        }
                        count += __popc(hm);
                    }
                    if (count >= NSAMPLE) break;
                    // ---- process B ----
                    if (mB >= 0) {
                        #pragma unroll
                        for (int c = 0; c < NCH; c++) {
                            int k = k0 + c * 32 + lane;
                            float dx = px - axB[c];
                            float dy = py - ayB[c];
                            float dz = pz - azB[c];
                            bool hit = (dx * dx + dy * dy + dz * dz) <= RADIUS2;
                            unsigned hm = __ballot_sync(0xffffffffu, hit);
                            if (hit) {
                                int rank = count + __popc(hm & ((1u << lane) - 1u));
                                if (rank < NSAMPLE)
                                    g_ball[p * NSAMPLE + rank] =
                                        make_float4(dx, dy, dz,
                                                    (float)(base_flat + gmB * K + k));
                            }
                            count += __popc(hm);
                        }
                        if (count >= NSAMPLE) break;
                    }
                }
            }
        }
        if (lane == 0) g_count[p] = count < NSAMPLE ? count : NSAMPLE;
    }

    // ---- last block performs the exclusive scan (writes packed offc) ----
    __shared__ int s_last;
    __shared__ int s_wsum[8];
    __syncthreads();
    if (threadIdx.x == 0) {
        __threadfence();
        s_last = (atomicAdd(&g_done, 1) == PB - 1) ? 1 : 0;
    }
    __syncthreads();
    if (!s_last) return;

    {
        const int T = blockDim.x;            // 256
        int t    = threadIdx.x;
        int per  = (N + T - 1) / T;          // <= 32
        int base = t * per;
        int loc[32], cnt[32];
        int sum = 0;
        for (int i = 0; i < per; i++) {
            int idx = base + i;
            int v = (idx < N) ? g_count[idx] : 0;
            loc[i] = sum; cnt[i] = v;
            sum += v;
        }
        int l2 = t & 31, w = t >> 5;
        int x = sum;
        #pragma unroll
        for (int off = 1; off < 32; off <<= 1) {
            int y = __shfl_up_sync(0xffffffffu, x, off);
            if (l2 >= off) x += y;
        }
        if (l2 == 31) s_wsum[w] = x;
        __syncthreads();
        if (w == 0 && l2 < 8) {
            int v = s_wsum[l2];
            #pragma unroll
            for (int off = 1; off < 8; off <<= 1) {
                int y = __shfl_up_sync(0xffu, v, off);
                if (l2 >= off) v += y;
            }
            s_wsum[l2] = v;
        }
        __syncthreads();
        int excl = x - sum + (w > 0 ? s_wsum[w - 1] : 0);
        int run = excl;
        for (int i = 0; i < per; i++) {
            int idx = base + i;
            if (idx < N) g_offc[idx] = (run << 6) | cnt[i];
            run += cnt[i];
        }
        __syncthreads();
        if (threadIdx.x == 0) {
            int last = g_offc[N - 1];
            g_total = (last >> 6) + (last & 63);
            g_done  = 0;   // reset for next graph replay
        }
    }
}

// ---------------------------------------------------------------------------
// Kernel 2: blocks [0,WB): 2 warps per point, alternating rows; ball data
// loaded coalesced (float4/lane), no gathers. Blocks [WB, WB+ZB): grid-
// stride zero of the invalid tail using g_total.
// ---------------------------------------------------------------------------
__device__ __forceinline__ void zero_range(float* __restrict__ out,
                                           long start, long end,
                                           int bid, int nblk) {
    if (end <= start) return;
    long s4 = (start + 3) & ~3L;
    if (s4 > end) s4 = end;
    long e4 = s4 + (((end - s4) >> 2) << 2);
    if (bid == 0) {
        int head = (int)(s4 - start);
        if ((int)threadIdx.x < head) out[start + threadIdx.x] = 0.f;
        int tail = (int)(end - e4);
        if (threadIdx.x >= 4 && (int)threadIdx.x < 4 + tail)
            out[e4 + threadIdx.x - 4] = 0.f;
    }
    long n4 = (e4 - s4) >> 2;
    long stride = (long)nblk * blockDim.x;
    float4 z = make_float4(0.f, 0.f, 0.f, 0.f);
    for (long i = (long)bid * blockDim.x + threadIdx.x; i < n4; i += stride)
        reinterpret_cast<float4*>(out + s4)[i] = z;
}

__global__ void write_kernel(const float* __restrict__ features,
                             float* __restrict__ out,
                             int N, int C, int WB, int ZB, int write_idx,
                             long idx_base, long out_sz) {
    const int CC = 3 + C;   // 35

    if ((int)blockIdx.x >= WB) {
        int zb = blockIdx.x - WB;
        long total = (long)g_total;
        long gf_end = idx_base < out_sz ? idx_base : out_sz;
        zero_range(out, total * CC, gf_end, zb, ZB);
        if (out_sz > idx_base)
            zero_range(out, idx_base + total, out_sz, zb, ZB);
        return;
    }

    int tid  = threadIdx.x;
    int lane = tid & 31;
    int gw   = blockIdx.x * (blockDim.x >> 5) + (tid >> 5);
    int p    = gw >> 1;            // point
    int h    = gw & 1;             // half: rows h, h+2, ...
    if (p >= N) return;

    int packed = g_offc[p];
    int count  = packed & 63;
    if (count == 0) return;
    int off    = packed >> 6;

    // coalesced loads: features row (1 line), ball data (4 lines)
    float  f  = __ldg(&features[(size_t)p * C + lane]);
    float4 bd = g_ball[p * NSAMPLE + lane];

    float fshift = __shfl_sync(0xffffffffu, f, (lane - 3) & 31);
    float ftail  = __shfl_sync(0xffffffffu, f, (29 + lane) & 31);

    for (int r = h; r < count; r += 2) {
        float dx = __shfl_sync(0xffffffffu, bd.x, r);
        float dy = __shfl_sync(0xffffffffu, bd.y, r);
        float dz = __shfl_sync(0xffffffffu, bd.z, r);
        float v;
        if (lane == 0)      v = dx;
        else if (lane == 1) v = dy;
        else if (lane == 2) v = dz;
        else                v = fshift;
        float* o = out + (size_t)(off + r) * CC;
        o[lane] = v;
        if (lane < 3) o[32 + lane] = ftail;
    }

    if (write_idx && h == 1 && lane < count)
        out[idx_base + off + lane] = bd.w;
    if (write_idx && count == 1 && h == 0 && lane == 0)
        out[idx_base + off] = bd.w;   // count==1: h==1 warp has r-loop empty but still runs idx store; keep both safe
}

// ---------------------------------------------------------------------------
extern "C" void kernel_launch(void* const* d_in, const int* in_sizes, int n_in,
                              void* d_out, int out_size) {
    const float* xyz      = (const float*)d_in[0];
    const float* new_xyz  = (const float*)d_in[2];
    const float* rois     = (const float*)d_in[3];
    const float* features = (const float*)d_in[4];

    const int B  = in_sizes[1];
    const int N  = in_sizes[0] / 3;
    const int Nb = N / B;
    const int M  = in_sizes[3] / (B * 7);
    const int K  = in_sizes[2] / (B * M * 3);
    const int C  = in_sizes[4] / N;
    const long L = (long)N * NSAMPLE;
    const int CC = 3 + C;
    const int BM = B * M;

    float* out = (float*)d_out;

    const int TPB = 256;
    const int PB  = (N + (TPB >> 5) - 1) / (TPB >> 5);     // warp per point
    query_kernel<<<PB, TPB>>>(xyz, new_xyz, rois, PB, Nb, M, K, N, BM);

    const int WPB = TPB >> 5;                               // 8 warps/block
    const int WB  = (2 * N + WPB - 1) / WPB;                // 2 warps per point
    const int ZB  = 144;
    int write_idx = ((long)out_size >= L * CC + L) ? 1 : 0;
    write_kernel<<<WB + ZB, TPB>>>(features, out,
                                   N, C, WB, ZB, write_idx,
                                   L * (long)CC, (long)out_size);
}